// round 1
// baseline (speedup 1.0000x reference)
#include <cuda_runtime.h>
#include <cuda_bf16.h>
#include <cstdint>

#define NC 16
#define ND 128
#define HWSZ (512*512)
#define NBATCH 4
#define NPIX (NBATCH*HWSZ)
#define TILE 128
#define NTILES (NPIX/TILE)

// ---------------- precomputed folded weights (written by setup kernel) -------
__device__ float g_c1[128];                 // W0*feat_b + b0
__device__ float g_c2[16];                  // out_w*b1 + out_b
__device__ __nv_bfloat16 g_W1T[128 * 32];   // [n=128][k=32]: k<16 -> A[n][k]=(W0*feat_w), k>=16 -> Magg[n][k-16]=(adj*E)^T
__device__ __nv_bfloat16 g_W2T[16 * 144];   // [n=16][k=144]: k<128 -> Bw[n][k]=(out_w*W1), k>=128 -> S[n][k-128]=out_w*Magg

// ---------------- setup kernel: fold all constant matrices -------------------
__global__ void setup_kernel(const float* __restrict__ E,
                             const float* __restrict__ aw1, const float* __restrict__ ab1,
                             const float* __restrict__ aw2, const float* __restrict__ ab2,
                             const float* __restrict__ w0,  const float* __restrict__ b0,
                             const float* __restrict__ w1,  const float* __restrict__ b1,
                             const float* __restrict__ fw,  const float* __restrict__ fb,
                             const float* __restrict__ ow,  const float* __restrict__ ob) {
    __shared__ float e1s[16][64];
    __shared__ float e2s[16][64];
    __shared__ float adjs[16][16];
    __shared__ float rs[16];
    __shared__ float Maggs[128][16];
    const int tid = threadIdx.x;

    // e1 = relu(E @ aw1^T + ab1), e2 likewise  (16x64 each)
    for (int idx = tid; idx < 2048; idx += blockDim.x) {
        const int which = idx >> 10;
        const int i = (idx >> 6) & 15;
        const int k = idx & 63;
        const float* w = which ? aw2 : aw1;
        const float* b = which ? ab2 : ab1;
        float s = b[k];
        #pragma unroll 4
        for (int d = 0; d < 128; d++) s += E[i * 128 + d] * w[k * 128 + d];
        s = fmaxf(s, 0.0f);
        if (which) e2s[i][k] = s; else e1s[i][k] = s;
    }
    __syncthreads();

    // adj = sigmoid(e1 @ e2^T) + I
    for (int idx = tid; idx < 256; idx += blockDim.x) {
        const int i = idx >> 4, j = idx & 15;
        float s = 0.0f;
        #pragma unroll 4
        for (int k = 0; k < 64; k++) s += e1s[i][k] * e2s[j][k];
        adjs[i][j] = 1.0f / (1.0f + expf(-s)) + ((i == j) ? 1.0f : 0.0f);
    }
    __syncthreads();
    if (tid < 16) {
        float s = 0.0f;
        for (int j = 0; j < 16; j++) s += adjs[tid][j];
        rs[tid] = 1.0f / s;
    }
    __syncthreads();

    // Magg[j][c] = sum_i adjn[c][i] * E[i][j]     (= (adj@E)^T)
    for (int idx = tid; idx < 2048; idx += blockDim.x) {
        const int j = idx >> 4, c = idx & 15;
        float s = 0.0f;
        #pragma unroll
        for (int i = 0; i < 16; i++) s += adjs[c][i] * E[i * 128 + j];
        Maggs[j][c] = s * rs[c];
    }
    __syncthreads();

    // A = W0 @ feat_w -> W1T cols 0..15 ; Magg -> W1T cols 16..31
    for (int idx = tid; idx < 2048; idx += blockDim.x) {
        const int j = idx >> 4, c = idx & 15;
        float s = 0.0f;
        #pragma unroll 4
        for (int d = 0; d < 128; d++) s += w0[j * 128 + d] * fw[d * 16 + c];
        g_W1T[j * 32 + c]      = __float2bfloat16(s);
        g_W1T[j * 32 + 16 + c] = __float2bfloat16(Maggs[j][c]);
    }
    // c1 = W0 @ feat_b + b0
    for (int j = tid; j < 128; j += blockDim.x) {
        float s = b0[j];
        #pragma unroll 4
        for (int d = 0; d < 128; d++) s += w0[j * 128 + d] * fb[d];
        g_c1[j] = s;
    }
    // Bw = out_w @ W1 -> W2T cols 0..127
    for (int idx = tid; idx < 2048; idx += blockDim.x) {
        const int n = idx >> 7, d = idx & 127;
        float s = 0.0f;
        #pragma unroll 4
        for (int j = 0; j < 128; j++) s += ow[n * 128 + j] * w1[j * 128 + d];
        g_W2T[n * 144 + d] = __float2bfloat16(s);
    }
    // S = out_w @ Magg -> W2T cols 128..143
    for (int idx = tid; idx < 256; idx += blockDim.x) {
        const int n = idx >> 4, c = idx & 15;
        float s = 0.0f;
        #pragma unroll 4
        for (int j = 0; j < 128; j++) s += ow[n * 128 + j] * Maggs[j][c];
        g_W2T[n * 144 + 128 + c] = __float2bfloat16(s);
    }
    // c2 = out_w @ b1 + out_b
    if (tid < 16) {
        float s = ob[tid];
        #pragma unroll 4
        for (int j = 0; j < 128; j++) s += ow[tid * 128 + j] * b1[j];
        g_c2[tid] = s;
    }
}

// ---------------- mma helpers ------------------------------------------------
__device__ __forceinline__ uint32_t sptr(const void* p) {
    return (uint32_t)__cvta_generic_to_shared(p);
}
__device__ __forceinline__ void ldm4(uint32_t& r0, uint32_t& r1, uint32_t& r2, uint32_t& r3,
                                     uint32_t addr) {
    asm volatile("ldmatrix.sync.aligned.m8n8.x4.shared.b16 {%0,%1,%2,%3}, [%4];"
                 : "=r"(r0), "=r"(r1), "=r"(r2), "=r"(r3) : "r"(addr));
}
__device__ __forceinline__ void mma16816(float* c, const uint32_t* a, uint32_t b0, uint32_t b1) {
    asm volatile("mma.sync.aligned.m16n8k16.row.col.f32.bf16.bf16.f32 "
                 "{%0,%1,%2,%3}, {%4,%5,%6,%7}, {%8,%9}, {%0,%1,%2,%3};"
                 : "+f"(c[0]), "+f"(c[1]), "+f"(c[2]), "+f"(c[3])
                 : "r"(a[0]), "r"(a[1]), "r"(a[2]), "r"(a[3]), "r"(b0), "r"(b1));
}
__device__ __forceinline__ uint32_t packrelu2(float a, float b) {
    __nv_bfloat162 h = __floats2bfloat162_rn(fmaxf(a, 0.0f), fmaxf(b, 0.0f));
    return *reinterpret_cast<uint32_t*>(&h);
}

// ---------------- main kernel ------------------------------------------------
__global__ __launch_bounds__(256, 2)
void refine_kernel(const float* __restrict__ logits, float* __restrict__ out,
                   const float* __restrict__ gatep) {
    // smem: logits tile fp32 (row=ch, pad 132 -> 4-bank step, conflict-free),
    // packed [l|p] bf16 rows (pad 40 -> 20-bank step, conflict-free ldmatrix),
    // weights (pads chosen for conflict-free ldmatrix: 40 and 152 cols)
    __shared__ __align__(16) float Ls[16][132];
    __shared__ __align__(16) __nv_bfloat16 Xs[128][40];
    __shared__ __align__(16) __nv_bfloat16 W1s[128][40];
    __shared__ __align__(16) __nv_bfloat16 W2s[16][152];
    __shared__ float c1s[128];
    __shared__ float c2s[16];

    const int tid = threadIdx.x;
    const int lane = tid & 31;
    const int w = tid >> 5;          // warp 0..7, each owns 16 pixels of the tile
    const int g = lane >> 2;         // row group 0..7
    const int t = lane & 3;          // col quad 0..3

    // load folded weights once per CTA
    for (int i = tid; i < 128 * 32; i += 256) W1s[i >> 5][i & 31] = g_W1T[i];
    for (int i = tid; i < 16 * 144; i += 256) W2s[i / 144][i % 144] = g_W2T[i];
    if (tid < 128) c1s[tid] = g_c1[tid];
    if (tid < 16)  c2s[tid] = g_c2[tid];
    const float gate = *gatep;

    // ldmatrix lane-address components
    const int a_row = 16 * w + (lane & 15);
    const int a_col = (lane >= 16) ? 8 : 0;
    const int brow16 = (lane & 7) + ((lane >= 16) ? 8 : 0);
    const int bcol8 = (lane & 8) ? 8 : 0;
    const uint32_t xs_addr = sptr(&Xs[a_row][a_col]);

    __syncthreads();

    for (int tile = blockIdx.x; tile < NTILES; tile += gridDim.x) {
        const int pbase = tile * TILE;
        const int b = pbase >> 18;            // HWSZ = 2^18
        const int hw0 = pbase & (HWSZ - 1);
        const float* __restrict__ src = logits + (size_t)b * NC * HWSZ + hw0;

        // ---- load [16ch][128px] fp32, fully coalesced (float4) ----
        #pragma unroll
        for (int r = 0; r < 2; r++) {
            const int idx = tid + 256 * r;            // 0..511
            const int c = idx >> 5, v = idx & 31;
            const float4 val = *reinterpret_cast<const float4*>(src + (size_t)c * HWSZ + 4 * v);
            *reinterpret_cast<float4*>(&Ls[c][4 * v]) = val;
        }
        __syncthreads();

        // ---- per-pixel softmax, pack [l | p] as bf16 row ----
        if (tid < 128) {
            float l[16], e[16];
            float m = -1e30f;
            #pragma unroll
            for (int c = 0; c < 16; c++) { l[c] = Ls[c][tid]; m = fmaxf(m, l[c]); }
            float s = 0.0f;
            #pragma unroll
            for (int c = 0; c < 16; c++) { e[c] = __expf(l[c] - m); s += e[c]; }
            const float inv = 1.0f / s;
            __nv_bfloat162* xr = reinterpret_cast<__nv_bfloat162*>(&Xs[tid][0]);
            #pragma unroll
            for (int c = 0; c < 8; c++) xr[c] = __floats2bfloat162_rn(l[2 * c], l[2 * c + 1]);
            #pragma unroll
            for (int c = 0; c < 8; c++) xr[8 + c] = __floats2bfloat162_rn(e[2 * c] * inv, e[2 * c + 1] * inv);
        }
        __syncthreads();

        // ---- A fragments: logits block (k 0..15) and probs block (k 16..31) ----
        uint32_t aL[4], aP[4];
        ldm4(aL[0], aL[1], aL[2], aL[3], xs_addr);
        ldm4(aP[0], aP[1], aP[2], aP[3], xs_addr + 32);

        // ---- GEMM1: U[16,128] = [l|p] @ W1 + c1 ----
        float acc[16][4];
        #pragma unroll
        for (int nt = 0; nt < 16; nt++) {
            const float bv0 = c1s[8 * nt + 2 * t];
            const float bv1 = c1s[8 * nt + 2 * t + 1];
            acc[nt][0] = bv0; acc[nt][1] = bv1; acc[nt][2] = bv0; acc[nt][3] = bv1;
        }
        #pragma unroll
        for (int ntp = 0; ntp < 8; ntp++) {
            uint32_t r0, r1, r2, r3;
            ldm4(r0, r1, r2, r3, sptr(&W1s[16 * ntp + brow16][bcol8]));
            mma16816(acc[2 * ntp],     aL, r0, r1);
            mma16816(acc[2 * ntp + 1], aL, r2, r3);
            ldm4(r0, r1, r2, r3, sptr(&W1s[16 * ntp + brow16][16 + bcol8]));
            mma16816(acc[2 * ntp],     aP, r0, r1);
            mma16816(acc[2 * ntp + 1], aP, r2, r3);
        }

        // ---- GEMM2: R[16,16] = relu(U) @ Bw^T + p @ S^T + c2 ----
        // accumulator fragments of GEMM1 convert in-place into A fragments (no smem round trip)
        float racc[2][4];
        #pragma unroll
        for (int nt = 0; nt < 2; nt++) {
            const float bv0 = c2s[8 * nt + 2 * t];
            const float bv1 = c2s[8 * nt + 2 * t + 1];
            racc[nt][0] = bv0; racc[nt][1] = bv1; racc[nt][2] = bv0; racc[nt][3] = bv1;
        }
        #pragma unroll
        for (int kb = 0; kb < 8; kb++) {
            uint32_t h[4];
            h[0] = packrelu2(acc[2 * kb][0],     acc[2 * kb][1]);
            h[1] = packrelu2(acc[2 * kb][2],     acc[2 * kb][3]);
            h[2] = packrelu2(acc[2 * kb + 1][0], acc[2 * kb + 1][1]);
            h[3] = packrelu2(acc[2 * kb + 1][2], acc[2 * kb + 1][3]);
            uint32_t r0, r1, r2, r3;
            ldm4(r0, r1, r2, r3, sptr(&W2s[brow16][16 * kb + bcol8]));
            mma16816(racc[0], h, r0, r1);
            mma16816(racc[1], h, r2, r3);
        }
        {   // 9th k-block: probs against S
            uint32_t r0, r1, r2, r3;
            ldm4(r0, r1, r2, r3, sptr(&W2s[brow16][128 + bcol8]));
            mma16816(racc[0], aP, r0, r1);
            mma16816(racc[1], aP, r2, r3);
        }

        // ---- epilogue: out = gate*r + logits (residual from fp32 smem) ----
        float* __restrict__ dst = out + (size_t)b * NC * HWSZ + hw0 + 16 * w;
        #pragma unroll
        for (int nt = 0; nt < 2; nt++) {
            const int ch = 8 * nt + 2 * t;
            dst[(size_t)ch * HWSZ + g]           = fmaf(gate, racc[nt][0], Ls[ch][16 * w + g]);
            dst[(size_t)(ch + 1) * HWSZ + g]     = fmaf(gate, racc[nt][1], Ls[ch + 1][16 * w + g]);
            dst[(size_t)ch * HWSZ + g + 8]       = fmaf(gate, racc[nt][2], Ls[ch][16 * w + g + 8]);
            dst[(size_t)(ch + 1) * HWSZ + g + 8] = fmaf(gate, racc[nt][3], Ls[ch + 1][16 * w + g + 8]);
        }
        __syncthreads();   // protect Ls/Xs before next iteration overwrites
    }
}

// ---------------- launch -----------------------------------------------------
extern "C" void kernel_launch(void* const* d_in, const int* in_sizes, int n_in,
                              void* d_out, int out_size) {
    const float* logits = (const float*)d_in[0];
    const float* E      = (const float*)d_in[1];
    const float* aw1    = (const float*)d_in[2];
    const float* ab1    = (const float*)d_in[3];
    const float* aw2    = (const float*)d_in[4];
    const float* ab2    = (const float*)d_in[5];
    const float* w0     = (const float*)d_in[6];
    const float* b0     = (const float*)d_in[7];
    const float* w1     = (const float*)d_in[8];
    const float* b1     = (const float*)d_in[9];
    const float* fw     = (const float*)d_in[10];
    const float* fb     = (const float*)d_in[11];
    const float* ow     = (const float*)d_in[12];
    const float* ob     = (const float*)d_in[13];
    const float* gate   = (const float*)d_in[14];
    float* out = (float*)d_out;

    setup_kernel<<<1, 512>>>(E, aw1, ab1, aw2, ab2, w0, b0, w1, b1, fw, fb, ow, ob);
    refine_kernel<<<1184, 256>>>(logits, out, gate);
}

// round 2
// speedup vs baseline: 1.2575x; 1.2575x over previous
#include <cuda_runtime.h>
#include <cuda_bf16.h>
#include <cstdint>

#define NC 16
#define ND 128
#define HWSZ (512*512)
#define NBATCH 4
#define NPIX (NBATCH*HWSZ)
#define TILE 128
#define NTILES (NPIX/TILE)

// ---------------- precomputed folded weights -------------------------------
__device__ float g_c1[128];                 // W0*feat_b + b0
__device__ float g_c2[16];                  // out_w*b1 + out_b
__device__ float g_Magg[128 * 16];          // (adj_norm @ E)^T
__device__ __nv_bfloat16 g_W1T[128 * 32];   // [n=128][k=32]: k<16 -> W0*feat_w ; k>=16 -> Magg
__device__ __nv_bfloat16 g_W2T[16 * 144];   // [n=16][k=144]: k<128 -> out_w*W1 ; k>=128 -> out_w*Magg

// ---------------- setup stage A: adjacency + Magg (tiny, 1 CTA) ------------
__global__ void setup_a(const float* __restrict__ E,
                        const float* __restrict__ aw1, const float* __restrict__ ab1,
                        const float* __restrict__ aw2, const float* __restrict__ ab2) {
    __shared__ float e1s[16][64];
    __shared__ float e2s[16][64];
    __shared__ float adjs[16][16];
    __shared__ float rs[16];
    const int tid = threadIdx.x;

    for (int idx = tid; idx < 2048; idx += blockDim.x) {
        const int which = idx >> 10;
        const int i = (idx >> 6) & 15;
        const int k = idx & 63;
        const float* w = which ? aw2 : aw1;
        const float* b = which ? ab2 : ab1;
        float s = b[k];
        #pragma unroll 8
        for (int d = 0; d < 128; d++) s += E[i * 128 + d] * w[k * 128 + d];
        s = fmaxf(s, 0.0f);
        if (which) e2s[i][k] = s; else e1s[i][k] = s;
    }
    __syncthreads();

    for (int idx = tid; idx < 256; idx += blockDim.x) {
        const int i = idx >> 4, j = idx & 15;
        float s = 0.0f;
        #pragma unroll 8
        for (int k = 0; k < 64; k++) s += e1s[i][k] * e2s[j][k];
        adjs[i][j] = 1.0f / (1.0f + expf(-s)) + ((i == j) ? 1.0f : 0.0f);
    }
    __syncthreads();
    if (tid < 16) {
        float s = 0.0f;
        for (int j = 0; j < 16; j++) s += adjs[tid][j];
        rs[tid] = 1.0f / s;
    }
    __syncthreads();

    // Magg[j][c] = (1/rowsum_c) * sum_i adj[c][i] * E[i][j]
    for (int idx = tid; idx < 2048; idx += blockDim.x) {
        const int j = idx >> 4, c = idx & 15;
        float s = 0.0f;
        #pragma unroll
        for (int i = 0; i < 16; i++) s += adjs[c][i] * E[i * 128 + j];
        g_Magg[j * 16 + c] = s * rs[c];
    }
}

// ---------------- setup stage B: parallel weight folds (9 CTAs) ------------
__global__ void setup_b(const float* __restrict__ E,
                        const float* __restrict__ w0,  const float* __restrict__ b0,
                        const float* __restrict__ w1,  const float* __restrict__ b1,
                        const float* __restrict__ fw,  const float* __restrict__ fb,
                        const float* __restrict__ ow,  const float* __restrict__ ob) {
    const int tid = threadIdx.x;
    const int blk = blockIdx.x;
    if (blk < 4) {
        // Bw = out_w @ W1 -> W2T cols 0..127  (2048 outputs, 512 per block)
        #pragma unroll
        for (int r = 0; r < 2; r++) {
            const int idx = blk * 512 + tid + 256 * r;
            const int n = idx >> 7, d = idx & 127;
            float s = 0.0f;
            #pragma unroll 8
            for (int j = 0; j < 128; j++) s += ow[n * 128 + j] * w1[j * 128 + d];
            g_W2T[n * 144 + d] = __float2bfloat16(s);
        }
    } else if (blk < 8) {
        // A = W0 @ feat_w -> W1T cols 0..15
        #pragma unroll
        for (int r = 0; r < 2; r++) {
            const int idx = (blk - 4) * 512 + tid + 256 * r;
            const int j = idx >> 4, c = idx & 15;
            float s = 0.0f;
            #pragma unroll 8
            for (int d = 0; d < 128; d++) s += w0[j * 128 + d] * fw[d * 16 + c];
            g_W1T[j * 32 + c] = __float2bfloat16(s);
        }
    } else {
        // Magg copy -> W1T cols 16..31
        for (int i = tid; i < 2048; i += 256) {
            const int j = i >> 4, c = i & 15;
            g_W1T[j * 32 + 16 + c] = __float2bfloat16(g_Magg[i]);
        }
        // S = out_w @ Magg -> W2T cols 128..143
        for (int idx = tid; idx < 256; idx += 256) {
            const int n = idx >> 4, c = idx & 15;
            float s = 0.0f;
            #pragma unroll 8
            for (int j = 0; j < 128; j++) s += ow[n * 128 + j] * g_Magg[j * 16 + c];
            g_W2T[n * 144 + 128 + c] = __float2bfloat16(s);
        }
        // c1 = W0 @ feat_b + b0
        if (tid < 128) {
            float s = b0[tid];
            #pragma unroll 8
            for (int d = 0; d < 128; d++) s += w0[tid * 128 + d] * fb[d];
            g_c1[tid] = s;
        }
        // c2 = out_w @ b1 + out_b
        if (tid < 16) {
            float s = ob[tid];
            #pragma unroll 8
            for (int j = 0; j < 128; j++) s += ow[tid * 128 + j] * b1[j];
            g_c2[tid] = s;
        }
    }
}

// ---------------- mma helpers ----------------------------------------------
__device__ __forceinline__ uint32_t sptr(const void* p) {
    return (uint32_t)__cvta_generic_to_shared(p);
}
__device__ __forceinline__ void ldm4(uint32_t& r0, uint32_t& r1, uint32_t& r2, uint32_t& r3,
                                     uint32_t addr) {
    asm volatile("ldmatrix.sync.aligned.m8n8.x4.shared.b16 {%0,%1,%2,%3}, [%4];"
                 : "=r"(r0), "=r"(r1), "=r"(r2), "=r"(r3) : "r"(addr));
}
__device__ __forceinline__ void mma16816(float* c, const uint32_t* a, uint32_t b0, uint32_t b1) {
    asm volatile("mma.sync.aligned.m16n8k16.row.col.f32.bf16.bf16.f32 "
                 "{%0,%1,%2,%3}, {%4,%5,%6,%7}, {%8,%9}, {%0,%1,%2,%3};"
                 : "+f"(c[0]), "+f"(c[1]), "+f"(c[2]), "+f"(c[3])
                 : "r"(a[0]), "r"(a[1]), "r"(a[2]), "r"(a[3]), "r"(b0), "r"(b1));
}
__device__ __forceinline__ uint32_t packrelu2(float a, float b) {
    __nv_bfloat162 h = __floats2bfloat162_rn(fmaxf(a, 0.0f), fmaxf(b, 0.0f));
    return *reinterpret_cast<uint32_t*>(&h);
}

// ---------------- main kernel: persistent CTAs, register-resident weights ---
__global__ __launch_bounds__(256)
void refine_kernel(const float* __restrict__ logits, float* __restrict__ out,
                   const float* __restrict__ gatep) {
    __shared__ __align__(16) float Ls[2][16][136];          // double-buffered logits tile
    __shared__ __align__(16) __nv_bfloat16 Xs[128][40];     // packed [l|p] rows
    __shared__ __align__(16) __nv_bfloat16 W1s[128][40];    // staging only (prologue)
    __shared__ __align__(16) __nv_bfloat16 W2s[16][152];    // staging only (prologue)
    __shared__ float c1s[128];
    __shared__ float c2s[16];

    const int tid = threadIdx.x;
    const int lane = tid & 31;
    const int w = tid >> 5;          // warp 0..7, each owns 16 pixels of the tile
    const int g = lane >> 2;         // row group 0..7
    const int t = lane & 3;          // col quad 0..3

    // ---- prologue: stage folded weights into smem, then into register frags
    for (int i = tid; i < 128 * 32; i += 256) W1s[i >> 5][i & 31] = g_W1T[i];
    for (int i = tid; i < 16 * 144; i += 256) W2s[i / 144][i % 144] = g_W2T[i];
    if (tid < 128) c1s[tid] = g_c1[tid];
    if (tid < 16)  c2s[tid] = g_c2[tid];
    const float gate = *gatep;

    const int a_row = 16 * w + (lane & 15);
    const int a_col = (lane >= 16) ? 8 : 0;
    const int brow16 = (lane & 7) + ((lane >= 16) ? 8 : 0);
    const int bcol8 = (lane & 8) ? 8 : 0;
    const uint32_t xs_addr = sptr(&Xs[a_row][a_col]);

    __syncthreads();

    uint32_t fW1[8][8];   // [n16-pair][0..3 = logits k-block, 4..7 = probs k-block]
    #pragma unroll
    for (int ntp = 0; ntp < 8; ntp++) {
        ldm4(fW1[ntp][0], fW1[ntp][1], fW1[ntp][2], fW1[ntp][3],
             sptr(&W1s[16 * ntp + brow16][bcol8]));
        ldm4(fW1[ntp][4], fW1[ntp][5], fW1[ntp][6], fW1[ntp][7],
             sptr(&W1s[16 * ntp + brow16][16 + bcol8]));
    }
    uint32_t fW2[9][4];   // 8 hidden k-blocks + 1 probs k-block
    #pragma unroll
    for (int kb = 0; kb < 8; kb++)
        ldm4(fW2[kb][0], fW2[kb][1], fW2[kb][2], fW2[kb][3],
             sptr(&W2s[brow16][16 * kb + bcol8]));
    ldm4(fW2[8][0], fW2[8][1], fW2[8][2], fW2[8][3],
         sptr(&W2s[brow16][128 + bcol8]));

    // ---- prefetch helper: 8KB logits tile via cp.async (2 x 16B per thread)
    auto prefetch = [&](int tl, int bsel) {
        const int pbase = tl * TILE;
        const int b = pbase >> 18;
        const int hw0 = pbase & (HWSZ - 1);
        const float* __restrict__ src = logits + (size_t)b * NC * HWSZ + hw0;
        #pragma unroll
        for (int r = 0; r < 2; r++) {
            const int idx = tid + 256 * r;      // 0..511
            const int c = idx >> 5, v = idx & 31;
            const uint32_t daddr = sptr(&Ls[bsel][c][4 * v]);
            const float* sp = src + (size_t)c * HWSZ + 4 * v;
            asm volatile("cp.async.cg.shared.global [%0], [%1], 16;" :: "r"(daddr), "l"(sp));
        }
        asm volatile("cp.async.commit_group;");
    };

    const int stride = gridDim.x;
    int tile = blockIdx.x;
    prefetch(tile, 0);
    int buf = 0;

    for (; tile < NTILES; tile += stride) {
        int nxt = tile + stride;
        if (nxt >= NTILES) nxt = tile;          // clamp: harmless redundant load
        prefetch(nxt, buf ^ 1);
        asm volatile("cp.async.wait_group 1;");
        __syncthreads();

        // ---- per-pixel softmax, pack [l | p] as bf16 row ----
        if (tid < 128) {
            float l[16], e[16];
            float m = -1e30f;
            #pragma unroll
            for (int c = 0; c < 16; c++) { l[c] = Ls[buf][c][tid]; m = fmaxf(m, l[c]); }
            float s = 0.0f;
            #pragma unroll
            for (int c = 0; c < 16; c++) { e[c] = __expf(l[c] - m); s += e[c]; }
            const float inv = 1.0f / s;
            __nv_bfloat162* xr = reinterpret_cast<__nv_bfloat162*>(&Xs[tid][0]);
            #pragma unroll
            for (int c = 0; c < 8; c++) xr[c] = __floats2bfloat162_rn(l[2 * c], l[2 * c + 1]);
            #pragma unroll
            for (int c = 0; c < 8; c++) xr[8 + c] = __floats2bfloat162_rn(e[2 * c] * inv, e[2 * c + 1] * inv);
        }
        __syncthreads();

        // ---- A fragments: logits (k 0..15), probs (k 16..31) ----
        uint32_t aL[4], aP[4];
        ldm4(aL[0], aL[1], aL[2], aL[3], xs_addr);
        ldm4(aP[0], aP[1], aP[2], aP[3], xs_addr + 32);

        // ---- GEMM1: U[16,128] = [l|p] @ W1 + c1 (B in registers) ----
        float acc[16][4];
        #pragma unroll
        for (int nt = 0; nt < 16; nt++) {
            const float bv0 = c1s[8 * nt + 2 * t];
            const float bv1 = c1s[8 * nt + 2 * t + 1];
            acc[nt][0] = bv0; acc[nt][1] = bv1; acc[nt][2] = bv0; acc[nt][3] = bv1;
        }
        #pragma unroll
        for (int ntp = 0; ntp < 8; ntp++) {
            mma16816(acc[2 * ntp],     aL, fW1[ntp][0], fW1[ntp][1]);
            mma16816(acc[2 * ntp + 1], aL, fW1[ntp][2], fW1[ntp][3]);
            mma16816(acc[2 * ntp],     aP, fW1[ntp][4], fW1[ntp][5]);
            mma16816(acc[2 * ntp + 1], aP, fW1[ntp][6], fW1[ntp][7]);
        }

        // ---- GEMM2: R[16,16] = relu(U) @ Bw^T + p @ S^T + c2 ----
        float racc[2][4];
        #pragma unroll
        for (int nt = 0; nt < 2; nt++) {
            const float bv0 = c2s[8 * nt + 2 * t];
            const float bv1 = c2s[8 * nt + 2 * t + 1];
            racc[nt][0] = bv0; racc[nt][1] = bv1; racc[nt][2] = bv0; racc[nt][3] = bv1;
        }
        #pragma unroll
        for (int kb = 0; kb < 8; kb++) {
            uint32_t h[4];
            h[0] = packrelu2(acc[2 * kb][0],     acc[2 * kb][1]);
            h[1] = packrelu2(acc[2 * kb][2],     acc[2 * kb][3]);
            h[2] = packrelu2(acc[2 * kb + 1][0], acc[2 * kb + 1][1]);
            h[3] = packrelu2(acc[2 * kb + 1][2], acc[2 * kb + 1][3]);
            mma16816(racc[0], h, fW2[kb][0], fW2[kb][1]);
            mma16816(racc[1], h, fW2[kb][2], fW2[kb][3]);
        }
        mma16816(racc[0], aP, fW2[8][0], fW2[8][1]);
        mma16816(racc[1], aP, fW2[8][2], fW2[8][3]);

        // ---- epilogue: out = gate*r + logits (residual from fp32 smem) ----
        {
            const int pbase = tile * TILE;
            const int b = pbase >> 18;
            const int hw0 = pbase & (HWSZ - 1);
            float* __restrict__ dst = out + (size_t)b * NC * HWSZ + hw0 + 16 * w;
            #pragma unroll
            for (int nt = 0; nt < 2; nt++) {
                const int ch = 8 * nt + 2 * t;
                dst[(size_t)ch * HWSZ + g]           = fmaf(gate, racc[nt][0], Ls[buf][ch][16 * w + g]);
                dst[(size_t)(ch + 1) * HWSZ + g]     = fmaf(gate, racc[nt][1], Ls[buf][ch + 1][16 * w + g]);
                dst[(size_t)ch * HWSZ + g + 8]       = fmaf(gate, racc[nt][2], Ls[buf][ch][16 * w + g + 8]);
                dst[(size_t)(ch + 1) * HWSZ + g + 8] = fmaf(gate, racc[nt][3], Ls[buf][ch + 1][16 * w + g + 8]);
            }
        }
        __syncthreads();   // protect Ls[buf]/Xs before reuse
        buf ^= 1;
    }
}

// ---------------- launch -----------------------------------------------------
extern "C" void kernel_launch(void* const* d_in, const int* in_sizes, int n_in,
                              void* d_out, int out_size) {
    const float* logits = (const float*)d_in[0];
    const float* E      = (const float*)d_in[1];
    const float* aw1    = (const float*)d_in[2];
    const float* ab1    = (const float*)d_in[3];
    const float* aw2    = (const float*)d_in[4];
    const float* ab2    = (const float*)d_in[5];
    const float* w0     = (const float*)d_in[6];
    const float* b0     = (const float*)d_in[7];
    const float* w1     = (const float*)d_in[8];
    const float* b1     = (const float*)d_in[9];
    const float* fw     = (const float*)d_in[10];
    const float* fb     = (const float*)d_in[11];
    const float* ow     = (const float*)d_in[12];
    const float* ob     = (const float*)d_in[13];
    const float* gate   = (const float*)d_in[14];
    float* out = (float*)d_out;

    setup_a<<<1, 256>>>(E, aw1, ab1, aw2, ab2);
    setup_b<<<9, 256>>>(E, w0, b0, w1, b1, fw, fb, ow, ob);
    refine_kernel<<<148, 256>>>(logits, out, gate);
}

// round 4
// speedup vs baseline: 2.7889x; 2.2179x over previous
#include <cuda_runtime.h>
#include <cuda_bf16.h>
#include <cstdint>

#define NC 16
#define ND 128
#define HWSZ (512*512)
#define NBATCH 4
#define NPIX (NBATCH*HWSZ)
#define TILE 128
#define NTILES (NPIX/TILE)

// ---------------- precomputed folded weights -------------------------------
__device__ float g_e1[16 * 64];             // relu(E @ aw1^T + ab1)
__device__ float g_e2[16 * 64];             // relu(E @ aw2^T + ab2)
__device__ float g_c1[128];                 // W0*feat_b + b0
__device__ float g_c2[16];                  // out_w*b1 + out_b
__device__ float g_Magg[128 * 16];          // (adj_norm @ E)^T
__device__ __nv_bfloat16 g_W1T[128 * 32];   // [n=128][k=32]: k<16 -> W0*feat_w ; k>=16 -> Magg
__device__ __nv_bfloat16 g_W2T[16 * 144];   // [n=16][k=144]: k<128 -> out_w*W1 ; k>=128 -> out_w*Magg

// ---------------- setup a1: e1/e2 via warp-per-output, float4 lanes --------
__global__ void setup_a1(const float* __restrict__ E,
                         const float* __restrict__ aw1, const float* __restrict__ ab1,
                         const float* __restrict__ aw2, const float* __restrict__ ab2) {
    const int lane = threadIdx.x & 31;
    const int warp = (blockIdx.x << 3) | (threadIdx.x >> 5);   // 0..127 global warp
    // 2048 outputs, 128 warps -> 16 outputs per warp
    for (int r = 0; r < 16; r++) {
        const int o = warp * 16 + r;
        const int which = o >> 10;
        const int i = (o >> 6) & 15;
        const int k = o & 63;
        const float* __restrict__ w = which ? aw2 : aw1;
        const float4 ev = *reinterpret_cast<const float4*>(E + i * 128 + 4 * lane);
        const float4 wv = *reinterpret_cast<const float4*>(w + k * 128 + 4 * lane);
        float s = ev.x * wv.x + ev.y * wv.y + ev.z * wv.z + ev.w * wv.w;
        #pragma unroll
        for (int d = 16; d > 0; d >>= 1) s += __shfl_xor_sync(0xffffffffu, s, d);
        if (lane == 0) {
            const float* b = which ? ab2 : ab1;
            const float v = fmaxf(s + b[k], 0.0f);
            if (which) g_e2[i * 64 + k] = v; else g_e1[i * 64 + k] = v;
        }
    }
}

// ---------------- setup a2: adjacency + Magg (1 CTA, smem) -----------------
__global__ void setup_a2(const float* __restrict__ E) {
    __shared__ float e1s[16][64];
    __shared__ float e2s[16][64];
    __shared__ float adjs[16][16];
    __shared__ float rs[16];
    const int tid = threadIdx.x;

    for (int i = tid; i < 1024; i += 256) {
        e1s[i >> 6][i & 63] = g_e1[i];
        e2s[i >> 6][i & 63] = g_e2[i];
    }
    __syncthreads();

    // adj = sigmoid(e1 @ e2^T) + I   (256 outputs, thread each, smem operands)
    {
        const int i = tid >> 4, j = tid & 15;
        float s0 = 0.f, s1 = 0.f, s2 = 0.f, s3 = 0.f;
        #pragma unroll
        for (int k = 0; k < 64; k += 4) {
            s0 += e1s[i][k]     * e2s[j][k];
            s1 += e1s[i][k + 1] * e2s[j][k + 1];
            s2 += e1s[i][k + 2] * e2s[j][k + 2];
            s3 += e1s[i][k + 3] * e2s[j][k + 3];
        }
        const float s = (s0 + s1) + (s2 + s3);
        adjs[i][j] = 1.0f / (1.0f + expf(-s)) + ((i == j) ? 1.0f : 0.0f);
    }
    __syncthreads();
    if (tid < 16) {
        float s = 0.0f;
        #pragma unroll
        for (int j = 0; j < 16; j++) s += adjs[tid][j];
        rs[tid] = 1.0f / s;
    }
    __syncthreads();

    // Magg[j][c] = rs[c] * sum_i adjs[c][i]*E[i][j] ; also write W1T cols 16..31
    for (int idx = tid; idx < 2048; idx += 256) {
        const int c = idx >> 7, j = idx & 127;      // j fast -> coalesced E reads
        float s = 0.0f;
        #pragma unroll
        for (int i = 0; i < 16; i++) s += adjs[c][i] * E[i * 128 + j];
        s *= rs[c];
        g_Magg[j * 16 + c] = s;
        g_W1T[j * 32 + 16 + c] = __float2bfloat16(s);
    }
}

// ---------------- setup b: parallel weight folds (17 CTAs) -----------------
__global__ void setup_b(const float* __restrict__ E,
                        const float* __restrict__ w0,  const float* __restrict__ b0,
                        const float* __restrict__ w1,  const float* __restrict__ b1,
                        const float* __restrict__ fw,  const float* __restrict__ fb,
                        const float* __restrict__ ow,  const float* __restrict__ ob) {
    const int tid = threadIdx.x;
    const int blk = blockIdx.x;
    if (blk < 8) {
        // Bw = out_w @ W1 -> W2T cols 0..127 (d fast -> w1 reads coalesced)
        const int idx = blk * 256 + tid;
        const int n = idx >> 7, d = idx & 127;
        float s0 = 0.f, s1 = 0.f, s2 = 0.f, s3 = 0.f;
        #pragma unroll
        for (int j = 0; j < 128; j += 4) {
            s0 += ow[n * 128 + j]     * w1[(j)     * 128 + d];
            s1 += ow[n * 128 + j + 1] * w1[(j + 1) * 128 + d];
            s2 += ow[n * 128 + j + 2] * w1[(j + 2) * 128 + d];
            s3 += ow[n * 128 + j + 3] * w1[(j + 3) * 128 + d];
        }
        g_W2T[n * 144 + d] = __float2bfloat16((s0 + s1) + (s2 + s3));
    } else if (blk < 16) {
        // A = W0 @ feat_w -> W1T cols 0..15 (c fast -> fw reads coalesced)
        const int idx = (blk - 8) * 256 + tid;
        const int j = idx >> 4, c = idx & 15;
        float s0 = 0.f, s1 = 0.f, s2 = 0.f, s3 = 0.f;
        #pragma unroll
        for (int d = 0; d < 128; d += 4) {
            s0 += w0[j * 128 + d]     * fw[(d)     * 16 + c];
            s1 += w0[j * 128 + d + 1] * fw[(d + 1) * 16 + c];
            s2 += w0[j * 128 + d + 2] * fw[(d + 2) * 16 + c];
            s3 += w0[j * 128 + d + 3] * fw[(d + 3) * 16 + c];
        }
        g_W1T[j * 32 + c] = __float2bfloat16((s0 + s1) + (s2 + s3));
    } else {
        // S = out_w @ Magg -> W2T cols 128..143 (256 outputs, thread each)
        {
            const int n = tid >> 4, c = tid & 15;
            float s0 = 0.f, s1 = 0.f, s2 = 0.f, s3 = 0.f;
            #pragma unroll
            for (int j = 0; j < 128; j += 4) {
                s0 += ow[n * 128 + j]     * g_Magg[(j)     * 16 + c];
                s1 += ow[n * 128 + j + 1] * g_Magg[(j + 1) * 16 + c];
                s2 += ow[n * 128 + j + 2] * g_Magg[(j + 2) * 16 + c];
                s3 += ow[n * 128 + j + 3] * g_Magg[(j + 3) * 16 + c];
            }
            g_W2T[n * 144 + 128 + c] = __float2bfloat16((s0 + s1) + (s2 + s3));
        }
        // c1 = W0 @ feat_b + b0
        if (tid < 128) {
            float s0 = b0[tid], s1 = 0.f, s2 = 0.f, s3 = 0.f;
            #pragma unroll
            for (int d = 0; d < 128; d += 4) {
                s0 += w0[tid * 128 + d]     * fb[d];
                s1 += w0[tid * 128 + d + 1] * fb[d + 1];
                s2 += w0[tid * 128 + d + 2] * fb[d + 2];
                s3 += w0[tid * 128 + d + 3] * fb[d + 3];
            }
            g_c1[tid] = (s0 + s1) + (s2 + s3);
        }
        // c2 = out_w @ b1 + out_b
        if (tid < 16) {
            float s0 = ob[tid], s1 = 0.f, s2 = 0.f, s3 = 0.f;
            #pragma unroll
            for (int j = 0; j < 128; j += 4) {
                s0 += ow[tid * 128 + j]     * b1[j];
                s1 += ow[tid * 128 + j + 1] * b1[j + 1];
                s2 += ow[tid * 128 + j + 2] * b1[j + 2];
                s3 += ow[tid * 128 + j + 3] * b1[j + 3];
            }
            g_c2[tid] = (s0 + s1) + (s2 + s3);
        }
    }
}

// ---------------- mma helpers ----------------------------------------------
__device__ __forceinline__ uint32_t sptr(const void* p) {
    return (uint32_t)__cvta_generic_to_shared(p);
}
__device__ __forceinline__ void ldm4(uint32_t& r0, uint32_t& r1, uint32_t& r2, uint32_t& r3,
                                     uint32_t addr) {
    asm volatile("ldmatrix.sync.aligned.m8n8.x4.shared.b16 {%0,%1,%2,%3}, [%4];"
                 : "=r"(r0), "=r"(r1), "=r"(r2), "=r"(r3) : "r"(addr));
}
__device__ __forceinline__ void mma16816(float* c, const uint32_t* a, uint32_t b0, uint32_t b1) {
    asm volatile("mma.sync.aligned.m16n8k16.row.col.f32.bf16.bf16.f32 "
                 "{%0,%1,%2,%3}, {%4,%5,%6,%7}, {%8,%9}, {%0,%1,%2,%3};"
                 : "+f"(c[0]), "+f"(c[1]), "+f"(c[2]), "+f"(c[3])
                 : "r"(a[0]), "r"(a[1]), "r"(a[2]), "r"(a[3]), "r"(b0), "r"(b1));
}
__device__ __forceinline__ uint32_t packrelu2(float a, float b) {
    __nv_bfloat162 h = __floats2bfloat162_rn(fmaxf(a, 0.0f), fmaxf(b, 0.0f));
    return *reinterpret_cast<uint32_t*>(&h);
}

// ---------------- main kernel: persistent CTAs, register-resident weights ---
__global__ __launch_bounds__(256)
void refine_kernel(const float* __restrict__ logits, float* __restrict__ out,
                   const float* __restrict__ gatep) {
    __shared__ __align__(16) float Ls[2][16][136];          // double-buffered logits tile
    __shared__ __align__(16) __nv_bfloat16 Xs[128][40];     // packed [l|p] rows
    __shared__ __align__(16) __nv_bfloat16 W1s[128][40];    // staging only (prologue)
    __shared__ __align__(16) __nv_bfloat16 W2s[16][152];    // staging only (prologue)
    __shared__ float c1s[128];
    __shared__ float c2s[16];

    const int tid = threadIdx.x;
    const int lane = tid & 31;
    const int w = tid >> 5;          // warp 0..7, each owns 16 pixels of the tile
    const int g = lane >> 2;         // row group 0..7
    const int t = lane & 3;          // col quad 0..3

    // ---- prologue: stage folded weights into smem, then into register frags
    for (int i = tid; i < 128 * 32; i += 256) W1s[i >> 5][i & 31] = g_W1T[i];
    for (int i = tid; i < 16 * 144; i += 256) W2s[i / 144][i % 144] = g_W2T[i];
    if (tid < 128) c1s[tid] = g_c1[tid];
    if (tid < 16)  c2s[tid] = g_c2[tid];
    const float gate = *gatep;

    const int a_row = 16 * w + (lane & 15);
    const int a_col = (lane >= 16) ? 8 : 0;
    const int brow16 = (lane & 7) + ((lane >= 16) ? 8 : 0);
    const int bcol8 = (lane & 8) ? 8 : 0;
    const uint32_t xs_addr = sptr(&Xs[a_row][a_col]);

    __syncthreads();

    uint32_t fW1[8][8];   // [n16-pair][0..3 = logits k-block, 4..7 = probs k-block]
    #pragma unroll
    for (int ntp = 0; ntp < 8; ntp++) {
        ldm4(fW1[ntp][0], fW1[ntp][1], fW1[ntp][2], fW1[ntp][3],
             sptr(&W1s[16 * ntp + brow16][bcol8]));
        ldm4(fW1[ntp][4], fW1[ntp][5], fW1[ntp][6], fW1[ntp][7],
             sptr(&W1s[16 * ntp + brow16][16 + bcol8]));
    }
    uint32_t fW2[9][4];   // 8 hidden k-blocks + 1 probs k-block
    #pragma unroll
    for (int kb = 0; kb < 8; kb++)
        ldm4(fW2[kb][0], fW2[kb][1], fW2[kb][2], fW2[kb][3],
             sptr(&W2s[brow16][16 * kb + bcol8]));
    ldm4(fW2[8][0], fW2[8][1], fW2[8][2], fW2[8][3],
         sptr(&W2s[brow16][128 + bcol8]));

    // ---- prefetch helper: 8KB logits tile via cp.async (2 x 16B per thread)
    auto prefetch = [&](int tl, int bsel) {
        const int pbase = tl * TILE;
        const int b = pbase >> 18;
        const int hw0 = pbase & (HWSZ - 1);
        const float* __restrict__ src = logits + (size_t)b * NC * HWSZ + hw0;
        #pragma unroll
        for (int r = 0; r < 2; r++) {
            const int idx = tid + 256 * r;      // 0..511
            const int c = idx >> 5, v = idx & 31;
            const uint32_t daddr = sptr(&Ls[bsel][c][4 * v]);
            const float* sp = src + (size_t)c * HWSZ + 4 * v;
            asm volatile("cp.async.cg.shared.global [%0], [%1], 16;" :: "r"(daddr), "l"(sp));
        }
        asm volatile("cp.async.commit_group;");
    };

    const int stride = gridDim.x;
    int tile = blockIdx.x;
    prefetch(tile, 0);
    int buf = 0;

    for (; tile < NTILES; tile += stride) {
        int nxt = tile + stride;
        if (nxt >= NTILES) nxt = tile;          // clamp: harmless redundant load
        prefetch(nxt, buf ^ 1);
        asm volatile("cp.async.wait_group 1;");
        __syncthreads();

        // ---- per-pixel softmax, pack [l | p] as bf16 row ----
        if (tid < 128) {
            float l[16], e[16];
            float m = -1e30f;
            #pragma unroll
            for (int c = 0; c < 16; c++) { l[c] = Ls[buf][c][tid]; m = fmaxf(m, l[c]); }
            float s = 0.0f;
            #pragma unroll
            for (int c = 0; c < 16; c++) { e[c] = __expf(l[c] - m); s += e[c]; }
            const float inv = 1.0f / s;
            __nv_bfloat162* xr = reinterpret_cast<__nv_bfloat162*>(&Xs[tid][0]);
            #pragma unroll
            for (int c = 0; c < 8; c++) xr[c] = __floats2bfloat162_rn(l[2 * c], l[2 * c + 1]);
            #pragma unroll
            for (int c = 0; c < 8; c++) xr[8 + c] = __floats2bfloat162_rn(e[2 * c] * inv, e[2 * c + 1] * inv);
        }
        __syncthreads();

        // ---- A fragments: logits (k 0..15), probs (k 16..31) ----
        uint32_t aL[4], aP[4];
        ldm4(aL[0], aL[1], aL[2], aL[3], xs_addr);
        ldm4(aP[0], aP[1], aP[2], aP[3], xs_addr + 32);

        // ---- GEMM1: U[16,128] = [l|p] @ W1 + c1 (B in registers) ----
        float acc[16][4];
        #pragma unroll
        for (int nt = 0; nt < 16; nt++) {
            const float bv0 = c1s[8 * nt + 2 * t];
            const float bv1 = c1s[8 * nt + 2 * t + 1];
            acc[nt][0] = bv0; acc[nt][1] = bv1; acc[nt][2] = bv0; acc[nt][3] = bv1;
        }
        #pragma unroll
        for (int ntp = 0; ntp < 8; ntp++) {
            mma16816(acc[2 * ntp],     aL, fW1[ntp][0], fW1[ntp][1]);
            mma16816(acc[2 * ntp + 1], aL, fW1[ntp][2], fW1[ntp][3]);
            mma16816(acc[2 * ntp],     aP, fW1[ntp][4], fW1[ntp][5]);
            mma16816(acc[2 * ntp + 1], aP, fW1[ntp][6], fW1[ntp][7]);
        }

        // ---- GEMM2: R[16,16] = relu(U) @ Bw^T + p @ S^T + c2 ----
        float racc[2][4];
        #pragma unroll
        for (int nt = 0; nt < 2; nt++) {
            const float bv0 = c2s[8 * nt + 2 * t];
            const float bv1 = c2s[8 * nt + 2 * t + 1];
            racc[nt][0] = bv0; racc[nt][1] = bv1; racc[nt][2] = bv0; racc[nt][3] = bv1;
        }
        #pragma unroll
        for (int kb = 0; kb < 8; kb++) {
            uint32_t h[4];
            h[0] = packrelu2(acc[2 * kb][0],     acc[2 * kb][1]);
            h[1] = packrelu2(acc[2 * kb][2],     acc[2 * kb][3]);
            h[2] = packrelu2(acc[2 * kb + 1][0], acc[2 * kb + 1][1]);
            h[3] = packrelu2(acc[2 * kb + 1][2], acc[2 * kb + 1][3]);
            mma16816(racc[0], h, fW2[kb][0], fW2[kb][1]);
            mma16816(racc[1], h, fW2[kb][2], fW2[kb][3]);
        }
        mma16816(racc[0], aP, fW2[8][0], fW2[8][1]);
        mma16816(racc[1], aP, fW2[8][2], fW2[8][3]);

        // ---- epilogue: out = gate*r + logits (residual from fp32 smem) ----
        {
            const int pbase = tile * TILE;
            const int b = pbase >> 18;
            const int hw0 = pbase & (HWSZ - 1);
            float* __restrict__ dst = out + (size_t)b * NC * HWSZ + hw0 + 16 * w;
            #pragma unroll
            for (int nt = 0; nt < 2; nt++) {
                const int ch = 8 * nt + 2 * t;
                dst[(size_t)ch * HWSZ + g]           = fmaf(gate, racc[nt][0], Ls[buf][ch][16 * w + g]);
                dst[(size_t)(ch + 1) * HWSZ + g]     = fmaf(gate, racc[nt][1], Ls[buf][ch + 1][16 * w + g]);
                dst[(size_t)ch * HWSZ + g + 8]       = fmaf(gate, racc[nt][2], Ls[buf][ch][16 * w + g + 8]);
                dst[(size_t)(ch + 1) * HWSZ + g + 8] = fmaf(gate, racc[nt][3], Ls[buf][ch + 1][16 * w + g + 8]);
            }
        }
        __syncthreads();   // protect Ls[buf]/Xs before reuse
        buf ^= 1;
    }
}

// ---------------- launch -----------------------------------------------------
extern "C" void kernel_launch(void* const* d_in, const int* in_sizes, int n_in,
                              void* d_out, int out_size) {
    const float* logits = (const float*)d_in[0];
    const float* E      = (const float*)d_in[1];
    const float* aw1    = (const float*)d_in[2];
    const float* ab1    = (const float*)d_in[3];
    const float* aw2    = (const float*)d_in[4];
    const float* ab2    = (const float*)d_in[5];
    const float* w0     = (const float*)d_in[6];
    const float* b0     = (const float*)d_in[7];
    const float* w1     = (const float*)d_in[8];
    const float* b1     = (const float*)d_in[9];
    const float* fw     = (const float*)d_in[10];
    const float* fb     = (const float*)d_in[11];
    const float* ow     = (const float*)d_in[12];
    const float* ob     = (const float*)d_in[13];
    const float* gate   = (const float*)d_in[14];
    float* out = (float*)d_out;

    setup_a1<<<16, 256>>>(E, aw1, ab1, aw2, ab2);
    setup_a2<<<1, 256>>>(E);
    setup_b<<<17, 256>>>(E, w0, b0, w1, b1, fw, fb, ow, ob);
    refine_kernel<<<148, 256>>>(logits, out, gate);
}